// round 1
// baseline (speedup 1.0000x reference)
#include <cuda_runtime.h>
#include <math.h>

// Problem constants
#define T_   4096
#define B_   8
#define D_   512
#define H_   8
#define BS_  64
#define NB_  64
#define DH_  64
#define M_   (T_*B_)    // 32768 rows
#define BD_  (B_*D_)    // 4096

// ---------------- scratch (static device globals; no allocations) ----------
__device__ float g_xc  [T_*B_*D_];
__device__ float g_q   [T_*B_*D_];
__device__ float g_k   [T_*B_*D_];
__device__ float g_v   [T_*B_*D_];
__device__ float g_attn[T_*B_*D_];
__device__ float g_x1  [T_*B_*D_];
__device__ float g_tmp [T_*B_*D_];
__device__ float g_h   [M_*2*D_];

// ---------------- depthwise conv(k=3) + residual + BatchNorm ---------------
__global__ void conv_bn_kernel(const float* __restrict__ x, const float* __restrict__ w,
                               const float* __restrict__ bg, const float* __restrict__ bb,
                               const float* __restrict__ bm, const float* __restrict__ bv)
{
    int idx = blockIdx.x * blockDim.x + threadIdx.x;     // t*BD_ + b*D_ + d
    int d = idx & (D_ - 1);
    int t = idx >> 12;                                   // / 4096
    float xc = x[idx];
    float xm = (t > 0)      ? x[idx - BD_] : 0.f;
    float xp = (t < T_ - 1) ? x[idx + BD_] : 0.f;
    float y = fmaf(xm, w[d*3+0], fmaf(xc, w[d*3+1], fmaf(xp, w[d*3+2], xc)));
    y = (y - bm[d]) * rsqrtf(bv[d] + 1e-5f) * bg[d] + bb[d];
    g_xc[idx] = y;
}

// ---------------- SGEMM: C[M,N] = A[M,K] @ B[K,N], fused epilogues ---------
// BM=128, BN=64, BK=16, 256 threads, 8x4 per thread.
// act: 0 = bias only, 1 = gelu(acc + bias). res != null -> add res[row*N+col].
#define BM 128
#define BN 64
#define BK 16

__global__ __launch_bounds__(256) void sgemm_kernel(
    const float* __restrict__ A, const float* __restrict__ Bm,
    const float* __restrict__ bias, const float* __restrict__ res,
    float* __restrict__ C, int M, int N, int K, int act)
{
    __shared__ float As[BK][BM + 4];
    __shared__ float Bs[BK][BN];
    const int tid = threadIdx.x;
    const int bm = blockIdx.y * BM;
    const int bn = blockIdx.x * BN;
    const int tm = (tid >> 4) * 8;
    const int tn = (tid & 15) * 4;

    float acc[8][4];
#pragma unroll
    for (int i = 0; i < 8; i++)
#pragma unroll
        for (int j = 0; j < 4; j++) acc[i][j] = 0.f;

    for (int k0 = 0; k0 < K; k0 += BK) {
        // A tile: 128x16 (store transposed As[k][m])
#pragma unroll
        for (int i = 0; i < 2; i++) {
            int ai = tid * 2 + i;                 // 0..511
            int ar = ai >> 2;                     // 0..127
            int ac = (ai & 3) * 4;                // 0,4,8,12
            float4 av = *(const float4*)(A + (size_t)(bm + ar) * K + k0 + ac);
            As[ac + 0][ar] = av.x;
            As[ac + 1][ar] = av.y;
            As[ac + 2][ar] = av.z;
            As[ac + 3][ar] = av.w;
        }
        // B tile: 16x64
        {
            int br = tid >> 4;                    // 0..15
            int bc = (tid & 15) * 4;
            *(float4*)&Bs[br][bc] = *(const float4*)(Bm + (size_t)(k0 + br) * N + bn + bc);
        }
        __syncthreads();
#pragma unroll
        for (int k = 0; k < BK; k++) {
            float4 a0 = *(const float4*)&As[k][tm];
            float4 a1 = *(const float4*)&As[k][tm + 4];
            float4 b4 = *(const float4*)&Bs[k][tn];
            float a[8] = {a0.x, a0.y, a0.z, a0.w, a1.x, a1.y, a1.z, a1.w};
            float b[4] = {b4.x, b4.y, b4.z, b4.w};
#pragma unroll
            for (int i = 0; i < 8; i++)
#pragma unroll
                for (int j = 0; j < 4; j++)
                    acc[i][j] = fmaf(a[i], b[j], acc[i][j]);
        }
        __syncthreads();
    }

    float4 bia = *(const float4*)(bias + bn + tn);
#pragma unroll
    for (int i = 0; i < 8; i++) {
        int row = bm + tm + i;
        float v0 = acc[i][0] + bia.x;
        float v1 = acc[i][1] + bia.y;
        float v2 = acc[i][2] + bia.z;
        float v3 = acc[i][3] + bia.w;
        if (act == 1) {
            v0 = 0.5f * v0 * (1.f + erff(v0 * 0.7071067811865475f));
            v1 = 0.5f * v1 * (1.f + erff(v1 * 0.7071067811865475f));
            v2 = 0.5f * v2 * (1.f + erff(v2 * 0.7071067811865475f));
            v3 = 0.5f * v3 * (1.f + erff(v3 * 0.7071067811865475f));
        }
        if (res) {
            float4 r4 = *(const float4*)(res + (size_t)row * N + bn + tn);
            v0 += r4.x; v1 += r4.y; v2 += r4.z; v3 += r4.w;
        }
        float4 o4 = make_float4(v0, v1, v2, v3);
        *(float4*)(C + (size_t)row * N + bn + tn) = o4;
    }
}

// ---------------- bucketed sparse attention --------------------------------
// grid (NB, H, B), 256 threads. smem: q[64][68], k[128][68], v[128][68], w[64][132]
#define QS_STRIDE 68
#define WS_STRIDE 132
#define ATTN_SMEM ((64*QS_STRIDE + 128*QS_STRIDE + 128*QS_STRIDE + 64*WS_STRIDE) * 4)

__global__ __launch_bounds__(256) void attn_kernel(
    const float* __restrict__ Q, const float* __restrict__ Kt, const float* __restrict__ V,
    const int* __restrict__ t_length, const int* __restrict__ rand_idx,
    float* __restrict__ O)
{
    extern __shared__ float sm[];
    float* qs = sm;                       // 64*68
    float* ks = qs + 64 * QS_STRIDE;      // 128*68
    float* vs = ks + 128 * QS_STRIDE;     // 128*68
    float* ws = vs + 128 * QS_STRIDE;     // 64*132

    const int nb = blockIdx.x, h = blockIdx.y, b = blockIdx.z;
    const int tid = threadIdx.x;
    const int lane = tid & 31, warp = tid >> 5;
    const int t0 = nb * BS_;
    const int rb = rand_idx[nb];
    const int tlen = t_length[b];
    const int base = b * D_ + h * DH_;

    // load q tile (64x64)
#pragma unroll
    for (int i = 0; i < 4; i++) {
        int idx = i * 256 + tid;              // 0..1023
        int r = idx >> 4;
        int c4 = (idx & 15) << 2;
        *(float4*)&qs[r * QS_STRIDE + c4] =
            *(const float4*)(Q + (size_t)(t0 + r) * BD_ + base + c4);
    }
    // load k,v tiles (128x64: own bucket rows 0..63, random bucket rows 64..127)
#pragma unroll
    for (int i = 0; i < 8; i++) {
        int idx = i * 256 + tid;              // 0..2047
        int r = idx >> 4;                     // 0..127
        int c4 = (idx & 15) << 2;
        int t = (r < 64) ? (t0 + r) : (rb * BS_ + r - 64);
        *(float4*)&ks[r * QS_STRIDE + c4] =
            *(const float4*)(Kt + (size_t)t * BD_ + base + c4);
        *(float4*)&vs[r * QS_STRIDE + c4] =
            *(const float4*)(V + (size_t)t * BD_ + base + c4);
    }
    __syncthreads();

    const int r0 = warp * 8;   // 8 query rows per warp

    // scores: acc[r][c] = q[r0+r] . k[c*32+lane]
    float acc[8][4];
#pragma unroll
    for (int r = 0; r < 8; r++)
#pragma unroll
        for (int c = 0; c < 4; c++) acc[r][c] = 0.f;

#pragma unroll
    for (int k4 = 0; k4 < 16; k4++) {
        float4 kk[4];
#pragma unroll
        for (int c = 0; c < 4; c++)
            kk[c] = *(const float4*)&ks[(c * 32 + lane) * QS_STRIDE + k4 * 4];
#pragma unroll
        for (int r = 0; r < 8; r++) {
            float4 qv = *(const float4*)&qs[(r0 + r) * QS_STRIDE + k4 * 4];
#pragma unroll
            for (int c = 0; c < 4; c++) {
                acc[r][c] = fmaf(qv.x, kk[c].x, acc[r][c]);
                acc[r][c] = fmaf(qv.y, kk[c].y, acc[r][c]);
                acc[r][c] = fmaf(qv.z, kk[c].z, acc[r][c]);
                acc[r][c] = fmaf(qv.w, kk[c].w, acc[r][c]);
            }
        }
    }

    // mask positions
    bool msk[4];
#pragma unroll
    for (int c = 0; c < 4; c++) {
        int jc = c * 32 + lane;
        int kp = (jc < 64) ? (t0 + jc) : (rb * BS_ + jc - 64);
        msk[c] = kp >= tlen;
    }

    // softmax per row (warp-wide over 128 keys; matches jax -1e9 semantics)
#pragma unroll
    for (int r = 0; r < 8; r++) {
        float s[4];
        float mx = -1e30f;
#pragma unroll
        for (int c = 0; c < 4; c++) {
            s[c] = msk[c] ? -1e9f : acc[r][c] * 0.125f;
            mx = fmaxf(mx, s[c]);
        }
#pragma unroll
        for (int off = 16; off; off >>= 1)
            mx = fmaxf(mx, __shfl_xor_sync(0xffffffffu, mx, off));
        float e[4], sum = 0.f;
#pragma unroll
        for (int c = 0; c < 4; c++) { e[c] = __expf(s[c] - mx); sum += e[c]; }
#pragma unroll
        for (int off = 16; off; off >>= 1)
            sum += __shfl_xor_sync(0xffffffffu, sum, off);
        float inv = 1.f / sum;
#pragma unroll
        for (int c = 0; c < 4; c++)
            ws[(r0 + r) * WS_STRIDE + c * 32 + lane] = e[c] * inv;
    }
    __syncwarp();

    // o = attnw @ v : lane covers dh = c*32+lane, c in {0,1}
    float acc2[8][2];
#pragma unroll
    for (int r = 0; r < 8; r++) { acc2[r][0] = 0.f; acc2[r][1] = 0.f; }

#pragma unroll
    for (int j4 = 0; j4 < 32; j4++) {
        int j = j4 * 4;
        float vv[4][2];
#pragma unroll
        for (int jj = 0; jj < 4; jj++) {
#pragma unroll
            for (int c = 0; c < 2; c++)
                vv[jj][c] = vs[(j + jj) * QS_STRIDE + c * 32 + lane];
        }
#pragma unroll
        for (int r = 0; r < 8; r++) {
            float4 w4 = *(const float4*)&ws[(r0 + r) * WS_STRIDE + j];
#pragma unroll
            for (int c = 0; c < 2; c++) {
                acc2[r][c] = fmaf(w4.x, vv[0][c], acc2[r][c]);
                acc2[r][c] = fmaf(w4.y, vv[1][c], acc2[r][c]);
                acc2[r][c] = fmaf(w4.z, vv[2][c], acc2[r][c]);
                acc2[r][c] = fmaf(w4.w, vv[3][c], acc2[r][c]);
            }
        }
    }

#pragma unroll
    for (int r = 0; r < 8; r++)
#pragma unroll
        for (int c = 0; c < 2; c++)
            O[(size_t)(t0 + r0 + r) * BD_ + base + c * 32 + lane] = acc2[r][c];
}

// ---------------- LayerNorm over D=512 per row -----------------------------
__global__ __launch_bounds__(128) void ln_kernel(const float* __restrict__ in,
    const float* __restrict__ g, const float* __restrict__ bta, float* __restrict__ out)
{
    int row = blockIdx.x;
    int tid = threadIdx.x;
    const float* p = in + (size_t)row * D_;
    float4 v = *(const float4*)(p + tid * 4);
    float s  = v.x + v.y + v.z + v.w;
    float ss = v.x * v.x + v.y * v.y + v.z * v.z + v.w * v.w;
#pragma unroll
    for (int off = 16; off; off >>= 1) {
        s  += __shfl_xor_sync(0xffffffffu, s,  off);
        ss += __shfl_xor_sync(0xffffffffu, ss, off);
    }
    __shared__ float sb[8];
    int w = tid >> 5;
    if ((tid & 31) == 0) { sb[w] = s; sb[4 + w] = ss; }
    __syncthreads();
    s  = sb[0] + sb[1] + sb[2] + sb[3];
    ss = sb[4] + sb[5] + sb[6] + sb[7];
    float mean = s * (1.f / D_);
    float var  = ss * (1.f / D_) - mean * mean;
    float inv  = rsqrtf(var + 1e-5f);
    float4 g4 = *(const float4*)(g + tid * 4);
    float4 b4 = *(const float4*)(bta + tid * 4);
    float4 o;
    o.x = (v.x - mean) * inv * g4.x + b4.x;
    o.y = (v.y - mean) * inv * g4.y + b4.y;
    o.z = (v.z - mean) * inv * g4.z + b4.z;
    o.w = (v.w - mean) * inv * g4.w + b4.w;
    *(float4*)(out + (size_t)row * D_ + tid * 4) = o;
}

// ---------------- launch ---------------------------------------------------
extern "C" void kernel_launch(void* const* d_in, const int* in_sizes, int n_in,
                              void* d_out, int out_size)
{
    const float* x      = (const float*)d_in[0];
    const int*   t_len  = (const int*)d_in[1];
    const int*   ridx   = (const int*)d_in[2];
    const float* conv_w = (const float*)d_in[3];
    const float* bn_g   = (const float*)d_in[4];
    const float* bn_b   = (const float*)d_in[5];
    const float* bn_m   = (const float*)d_in[6];
    const float* bn_v   = (const float*)d_in[7];
    const float* wq = (const float*)d_in[8];  const float* bq = (const float*)d_in[9];
    const float* wk = (const float*)d_in[10]; const float* bk = (const float*)d_in[11];
    const float* wv = (const float*)d_in[12]; const float* bv = (const float*)d_in[13];
    const float* wo = (const float*)d_in[14]; const float* bo = (const float*)d_in[15];
    const float* ln1g = (const float*)d_in[16]; const float* ln1b = (const float*)d_in[17];
    const float* w1 = (const float*)d_in[18]; const float* b1 = (const float*)d_in[19];
    const float* w2 = (const float*)d_in[20]; const float* b2 = (const float*)d_in[21];
    const float* ln2g = (const float*)d_in[22]; const float* ln2b = (const float*)d_in[23];
    float* out = (float*)d_out;

    float *xc, *q, *k, *v, *attn, *x1, *tmp, *hbuf;
    cudaGetSymbolAddress((void**)&xc,   g_xc);
    cudaGetSymbolAddress((void**)&q,    g_q);
    cudaGetSymbolAddress((void**)&k,    g_k);
    cudaGetSymbolAddress((void**)&v,    g_v);
    cudaGetSymbolAddress((void**)&attn, g_attn);
    cudaGetSymbolAddress((void**)&x1,   g_x1);
    cudaGetSymbolAddress((void**)&tmp,  g_tmp);
    cudaGetSymbolAddress((void**)&hbuf, g_h);

    cudaFuncSetAttribute(attn_kernel, cudaFuncAttributeMaxDynamicSharedMemorySize, ATTN_SMEM);

    // 1. conv + residual + BN
    conv_bn_kernel<<<(M_ * D_) / 256, 256>>>(x, conv_w, bn_g, bn_b, bn_m, bn_v);

    // 2. Q/K/V projections
    dim3 g512(D_ / BN, M_ / BM);         // (8, 256)
    sgemm_kernel<<<g512, 256>>>(xc, wq, bq, nullptr, q, M_, D_, D_, 0);
    sgemm_kernel<<<g512, 256>>>(xc, wk, bk, nullptr, k, M_, D_, D_, 0);
    sgemm_kernel<<<g512, 256>>>(xc, wv, bv, nullptr, v, M_, D_, D_, 0);

    // 3. bucketed sparse attention
    attn_kernel<<<dim3(NB_, H_, B_), 256, ATTN_SMEM>>>(q, k, v, t_len, ridx, attn);

    // 4. output projection + bias + residual(xc), then LN1
    sgemm_kernel<<<g512, 256>>>(attn, wo, bo, xc, tmp, M_, D_, D_, 0);
    ln_kernel<<<M_, 128>>>(tmp, ln1g, ln1b, x1);

    // 5. MLP: gelu(x1@w1+b1) @ w2 + b2 + x1, then LN2 -> out
    dim3 g1024((2 * D_) / BN, M_ / BM);  // (16, 256)
    sgemm_kernel<<<g1024, 256>>>(x1, w1, b1, nullptr, hbuf, M_, 2 * D_, D_, 1);
    sgemm_kernel<<<g512, 256>>>(hbuf, w2, b2, x1, tmp, M_, D_, 2 * D_, 0);
    ln_kernel<<<M_, 128>>>(tmp, ln2g, ln2b, out);
}

// round 3
// speedup vs baseline: 1.1664x; 1.1664x over previous
#include <cuda_runtime.h>
#include <cstdint>
#include <math.h>

// Problem constants
#define T_   4096
#define B_   8
#define D_   512
#define H_   8
#define BS_  64
#define NB_  64
#define DH_  64
#define M_   (T_*B_)    // 32768 rows
#define BD_  (B_*D_)    // 4096

// ---------------- scratch (static device globals; no allocations) ----------
__device__ float g_xc  [T_*B_*D_];
__device__ float g_q   [T_*B_*D_];
__device__ float g_k   [T_*B_*D_];
__device__ float g_v   [T_*B_*D_];
__device__ float g_attn[T_*B_*D_];
__device__ float g_x1  [T_*B_*D_];
__device__ float g_tmp [T_*B_*D_];
__device__ float g_h   [M_*2*D_];
// transposed weights [N, K]
__device__ float g_wtq [D_*D_];
__device__ float g_wtk [D_*D_];
__device__ float g_wtv [D_*D_];
__device__ float g_wto [D_*D_];
__device__ float g_wt1 [2*D_*D_];
__device__ float g_wt2 [D_*2*D_];

// ---------------- depthwise conv(k=3) + residual + BatchNorm ---------------
__global__ void conv_bn_kernel(const float* __restrict__ x, const float* __restrict__ w,
                               const float* __restrict__ bg, const float* __restrict__ bb,
                               const float* __restrict__ bm, const float* __restrict__ bv)
{
    int idx = blockIdx.x * blockDim.x + threadIdx.x;
    int d = idx & (D_ - 1);
    int t = idx >> 12;
    float xc = x[idx];
    float xm = (t > 0)      ? x[idx - BD_] : 0.f;
    float xp = (t < T_ - 1) ? x[idx + BD_] : 0.f;
    float y = fmaf(xm, w[d*3+0], fmaf(xc, w[d*3+1], fmaf(xp, w[d*3+2], xc)));
    y = (y - bm[d]) * rsqrtf(bv[d] + 1e-5f) * bg[d] + bb[d];
    g_xc[idx] = y;
}

// ---------------- weight transpose: Wt[n*K+k] = W[k*N+n] -------------------
__global__ __launch_bounds__(256) void transpose_kernel(const float* __restrict__ W,
                                                        float* __restrict__ Wt, int K, int N)
{
    __shared__ float tile[32][33];
    int k0 = blockIdx.y * 32, n0 = blockIdx.x * 32;
    int tx = threadIdx.x & 31, ty = threadIdx.x >> 5;
#pragma unroll
    for (int i = 0; i < 32; i += 8)
        tile[ty + i][tx] = W[(size_t)(k0 + ty + i) * N + n0 + tx];
    __syncthreads();
#pragma unroll
    for (int i = 0; i < 32; i += 8)
        Wt[(size_t)(n0 + ty + i) * K + k0 + tx] = tile[tx][ty + i];
}

// ================= 3xTF32 mma.sync GEMM =====================================
// C[M,N] = A[M,K] @ Wt[N,K]^T, Wt row-major [N,K].
// grid(N/128, M/128), 256 threads. BM=BN=128, BK=32, double-buffered cp.async.
// Warp layout: warp_m = wid&1 (64 rows), warp_n = wid>>1 (32 cols).
// act: 0 = bias, 1 = gelu(acc+bias). res != null -> += res.

#define TSTR 36                 // smem float stride (bank-conflict-free fragments)
#define TILE_FLOATS (128 * TSTR)
#define GEMM_SMEM (2 * 2 * TILE_FLOATS * 4)   // 2 stages x (A,B) x 18432B

__device__ __forceinline__ void cp_async16(uint32_t dst, const void* src) {
    asm volatile("cp.async.ca.shared.global [%0], [%1], 16;" :: "r"(dst), "l"(src));
}
__device__ __forceinline__ void cp_commit() { asm volatile("cp.async.commit_group;"); }
template<int N> __device__ __forceinline__ void cp_wait() {
    asm volatile("cp.async.wait_group %0;" :: "n"(N));
}
__device__ __forceinline__ uint32_t smem_u32(const void* p) {
    uint32_t a;
    asm("{ .reg .u64 t; cvta.to.shared.u64 t, %1; cvt.u32.u64 %0, t; }" : "=r"(a) : "l"(p));
    return a;
}
__device__ __forceinline__ void tf32_split(float x, uint32_t& hi, uint32_t& lo) {
    asm("cvt.rna.tf32.f32 %0, %1;" : "=r"(hi) : "f"(x));
    float r = x - __uint_as_float(hi);
    asm("cvt.rna.tf32.f32 %0, %1;" : "=r"(lo) : "f"(r));
}
__device__ __forceinline__ void mma_tf32(float* c, uint32_t a0, uint32_t a1, uint32_t a2,
                                         uint32_t a3, uint32_t b0, uint32_t b1) {
    asm volatile(
        "mma.sync.aligned.m16n8k8.row.col.f32.tf32.tf32.f32 "
        "{%0,%1,%2,%3}, {%4,%5,%6,%7}, {%8,%9}, {%0,%1,%2,%3};"
        : "+f"(c[0]), "+f"(c[1]), "+f"(c[2]), "+f"(c[3])
        : "r"(a0), "r"(a1), "r"(a2), "r"(a3), "r"(b0), "r"(b1));
}

// prefetch one 128x32 fp32 tile into smem stage (stride TSTR floats)
__device__ __forceinline__ void tile_prefetch(const float* __restrict__ g, int ldk,
                                              uint32_t sdst, int tid) {
#pragma unroll
    for (int i = 0; i < 4; i++) {
        int fi = i * 256 + tid;          // float4 slot 0..1023
        int r  = fi >> 3;                // row 0..127
        int c4 = (fi & 7) * 4;           // col 0,4,...,28
        cp_async16(sdst + (r * TSTR + c4) * 4, g + (size_t)r * ldk + c4);
    }
}

__global__ __launch_bounds__(256) void tf32_gemm_kernel(
    const float* __restrict__ A, const float* __restrict__ Wt,
    const float* __restrict__ bias, const float* __restrict__ res,
    float* __restrict__ C, int M, int N, int K, int act)
{
    extern __shared__ float smem[];
    float* As[2] = { smem,                   smem + 2 * TILE_FLOATS };
    float* Bs[2] = { smem + TILE_FLOATS,     smem + 3 * TILE_FLOATS };

    const int tid  = threadIdx.x;
    const int wid  = tid >> 5, lane = tid & 31;
    const int wm   = (wid & 1) * 64;          // warp M offset
    const int wn   = (wid >> 1) * 32;         // warp N offset
    const int lr   = lane >> 2;               // 0..7
    const int lc   = lane & 3;                // 0..3
    const int bm   = blockIdx.y * 128, bn = blockIdx.x * 128;

    const float* Ab = A  + (size_t)bm * K;
    const float* Bb = Wt + (size_t)bn * K;
    const int NC = K >> 5;

    float acc[4][4][4];
#pragma unroll
    for (int mt = 0; mt < 4; mt++)
#pragma unroll
        for (int nt = 0; nt < 4; nt++)
#pragma unroll
            for (int j = 0; j < 4; j++) acc[mt][nt][j] = 0.f;

    uint32_t sA[2] = { smem_u32(As[0]), smem_u32(As[1]) };
    uint32_t sB[2] = { smem_u32(Bs[0]), smem_u32(Bs[1]) };

    // prefetch chunk 0
    tile_prefetch(Ab, K, sA[0], tid);
    tile_prefetch(Bb, K, sB[0], tid);
    cp_commit();

    for (int i = 0; i < NC; i++) {
        const int s = i & 1;
        if (i + 1 < NC) {
            tile_prefetch(Ab + (i + 1) * 32, K, sA[s ^ 1], tid);
            tile_prefetch(Bb + (i + 1) * 32, K, sB[s ^ 1], tid);
            cp_commit();
            cp_wait<1>();
        } else {
            cp_wait<0>();
        }
        __syncthreads();

        const float* a = As[s];
        const float* b = Bs[s];
#pragma unroll
        for (int ks = 0; ks < 4; ks++) {
            const int kc = ks * 8 + lc;
            // A fragments (4 m-tiles), split hi/lo
            uint32_t ah[4][4], al[4][4];
#pragma unroll
            for (int mt = 0; mt < 4; mt++) {
                const int r0 = wm + mt * 16 + lr;
                tf32_split(a[r0 * TSTR + kc],           ah[mt][0], al[mt][0]);
                tf32_split(a[(r0 + 8) * TSTR + kc],     ah[mt][1], al[mt][1]);
                tf32_split(a[r0 * TSTR + kc + 4],       ah[mt][2], al[mt][2]);
                tf32_split(a[(r0 + 8) * TSTR + kc + 4], ah[mt][3], al[mt][3]);
            }
            // B fragments (4 n-tiles), split hi/lo
            uint32_t bh[4][2], bl[4][2];
#pragma unroll
            for (int nt = 0; nt < 4; nt++) {
                const int n0 = wn + nt * 8 + lr;
                tf32_split(b[n0 * TSTR + kc],     bh[nt][0], bl[nt][0]);
                tf32_split(b[n0 * TSTR + kc + 4], bh[nt][1], bl[nt][1]);
            }
#pragma unroll
            for (int mt = 0; mt < 4; mt++)
#pragma unroll
                for (int nt = 0; nt < 4; nt++) {
                    float* c = acc[mt][nt];
                    mma_tf32(c, ah[mt][0], ah[mt][1], ah[mt][2], ah[mt][3], bh[nt][0], bh[nt][1]);
                    mma_tf32(c, ah[mt][0], ah[mt][1], ah[mt][2], ah[mt][3], bl[nt][0], bl[nt][1]);
                    mma_tf32(c, al[mt][0], al[mt][1], al[mt][2], al[mt][3], bh[nt][0], bh[nt][1]);
                }
        }
        __syncthreads();
    }

    // ------- epilogue: bias (+gelu) (+res) -------
#pragma unroll
    for (int mt = 0; mt < 4; mt++) {
        const int row0 = bm + wm + mt * 16 + lr;
#pragma unroll
        for (int nt = 0; nt < 4; nt++) {
            const int col = bn + wn + nt * 8 + lc * 2;
            const float bi0 = bias[col], bi1 = bias[col + 1];
#pragma unroll
            for (int half = 0; half < 2; half++) {
                const int row = row0 + half * 8;
                float v0 = acc[mt][nt][half * 2 + 0] + bi0;
                float v1 = acc[mt][nt][half * 2 + 1] + bi1;
                if (act == 1) {
                    v0 = 0.5f * v0 * (1.f + erff(v0 * 0.7071067811865475f));
                    v1 = 0.5f * v1 * (1.f + erff(v1 * 0.7071067811865475f));
                }
                if (res) {
                    float2 r2 = *(const float2*)(res + (size_t)row * N + col);
                    v0 += r2.x; v1 += r2.y;
                }
                *(float2*)(C + (size_t)row * N + col) = make_float2(v0, v1);
            }
        }
    }
}

// ---------------- bucketed sparse attention --------------------------------
#define QS_STRIDE 68
#define WS_STRIDE 132
#define ATTN_SMEM ((64*QS_STRIDE + 128*QS_STRIDE + 128*QS_STRIDE + 64*WS_STRIDE) * 4)

__global__ __launch_bounds__(256) void attn_kernel(
    const float* __restrict__ Q, const float* __restrict__ Kt, const float* __restrict__ V,
    const int* __restrict__ t_length, const int* __restrict__ rand_idx,
    float* __restrict__ O)
{
    extern __shared__ float sm[];
    float* qs = sm;
    float* ks = qs + 64 * QS_STRIDE;
    float* vs = ks + 128 * QS_STRIDE;
    float* ws = vs + 128 * QS_STRIDE;

    const int nb = blockIdx.x, h = blockIdx.y, b = blockIdx.z;
    const int tid = threadIdx.x;
    const int lane = tid & 31, warp = tid >> 5;
    const int t0 = nb * BS_;
    const int rb = rand_idx[nb];
    const int tlen = t_length[b];
    const int base = b * D_ + h * DH_;

#pragma unroll
    for (int i = 0; i < 4; i++) {
        int idx = i * 256 + tid;
        int r = idx >> 4;
        int c4 = (idx & 15) << 2;
        *(float4*)&qs[r * QS_STRIDE + c4] =
            *(const float4*)(Q + (size_t)(t0 + r) * BD_ + base + c4);
    }
#pragma unroll
    for (int i = 0; i < 8; i++) {
        int idx = i * 256 + tid;
        int r = idx >> 4;
        int c4 = (idx & 15) << 2;
        int t = (r < 64) ? (t0 + r) : (rb * BS_ + r - 64);
        *(float4*)&ks[r * QS_STRIDE + c4] =
            *(const float4*)(Kt + (size_t)t * BD_ + base + c4);
        *(float4*)&vs[r * QS_STRIDE + c4] =
            *(const float4*)(V + (size_t)t * BD_ + base + c4);
    }
    __syncthreads();

    const int r0 = warp * 8;
    float acc[8][4];
#pragma unroll
    for (int r = 0; r < 8; r++)
#pragma unroll
        for (int c = 0; c < 4; c++) acc[r][c] = 0.f;

#pragma unroll
    for (int k4 = 0; k4 < 16; k4++) {
        float4 kk[4];
#pragma unroll
        for (int c = 0; c < 4; c++)
            kk[c] = *(const float4*)&ks[(c * 32 + lane) * QS_STRIDE + k4 * 4];
#pragma unroll
        for (int r = 0; r < 8; r++) {
            float4 qv = *(const float4*)&qs[(r0 + r) * QS_STRIDE + k4 * 4];
#pragma unroll
            for (int c = 0; c < 4; c++) {
                acc[r][c] = fmaf(qv.x, kk[c].x, acc[r][c]);
                acc[r][c] = fmaf(qv.y, kk[c].y, acc[r][c]);
                acc[r][c] = fmaf(qv.z, kk[c].z, acc[r][c]);
                acc[r][c] = fmaf(qv.w, kk[c].w, acc[r][c]);
            }
        }
    }

    bool msk[4];
#pragma unroll
    for (int c = 0; c < 4; c++) {
        int jc = c * 32 + lane;
        int kp = (jc < 64) ? (t0 + jc) : (rb * BS_ + jc - 64);
        msk[c] = kp >= tlen;
    }

#pragma unroll
    for (int r = 0; r < 8; r++) {
        float s[4];
        float mx = -1e30f;
#pragma unroll
        for (int c = 0; c < 4; c++) {
            s[c] = msk[c] ? -1e9f : acc[r][c] * 0.125f;
            mx = fmaxf(mx, s[c]);
        }
#pragma unroll
        for (int off = 16; off; off >>= 1)
            mx = fmaxf(mx, __shfl_xor_sync(0xffffffffu, mx, off));
        float e[4], sum = 0.f;
#pragma unroll
        for (int c = 0; c < 4; c++) { e[c] = __expf(s[c] - mx); sum += e[c]; }
#pragma unroll
        for (int off = 16; off; off >>= 1)
            sum += __shfl_xor_sync(0xffffffffu, sum, off);
        float inv = 1.f / sum;
#pragma unroll
        for (int c = 0; c < 4; c++)
            ws[(r0 + r) * WS_STRIDE + c * 32 + lane] = e[c] * inv;
    }
    __syncwarp();

    float acc2[8][2];
#pragma unroll
    for (int r = 0; r < 8; r++) { acc2[r][0] = 0.f; acc2[r][1] = 0.f; }

#pragma unroll
    for (int j4 = 0; j4 < 32; j4++) {
        int j = j4 * 4;
        float vv[4][2];
#pragma unroll
        for (int jj = 0; jj < 4; jj++) {
#pragma unroll
            for (int c = 0; c < 2; c++)
                vv[jj][c] = vs[(j + jj) * QS_STRIDE + c * 32 + lane];
        }
#pragma unroll
        for (int r = 0; r < 8; r++) {
            float4 w4 = *(const float4*)&ws[(r0 + r) * WS_STRIDE + j];
#pragma unroll
            for (int c = 0; c < 2; c++) {
                acc2[r][c] = fmaf(w4.x, vv[0][c], acc2[r][c]);
                acc2[r][c] = fmaf(w4.y, vv[1][c], acc2[r][c]);
                acc2[r][c] = fmaf(w4.z, vv[2][c], acc2[r][c]);
                acc2[r][c] = fmaf(w4.w, vv[3][c], acc2[r][c]);
            }
        }
    }

#pragma unroll
    for (int r = 0; r < 8; r++)
#pragma unroll
        for (int c = 0; c < 2; c++)
            O[(size_t)(t0 + r0 + r) * BD_ + base + c * 32 + lane] = acc2[r][c];
}

// ---------------- LayerNorm over D=512 per row -----------------------------
__global__ __launch_bounds__(128) void ln_kernel(const float* __restrict__ in,
    const float* __restrict__ g, const float* __restrict__ bta, float* __restrict__ out)
{
    int row = blockIdx.x;
    int tid = threadIdx.x;
    const float* p = in + (size_t)row * D_;
    float4 v = *(const float4*)(p + tid * 4);
    float s  = v.x + v.y + v.z + v.w;
    float ss = v.x * v.x + v.y * v.y + v.z * v.z + v.w * v.w;
#pragma unroll
    for (int off = 16; off; off >>= 1) {
        s  += __shfl_xor_sync(0xffffffffu, s,  off);
        ss += __shfl_xor_sync(0xffffffffu, ss, off);
    }
    __shared__ float sb[8];
    int w = tid >> 5;
    if ((tid & 31) == 0) { sb[w] = s; sb[4 + w] = ss; }
    __syncthreads();
    s  = sb[0] + sb[1] + sb[2] + sb[3];
    ss = sb[4] + sb[5] + sb[6] + sb[7];
    float mean = s * (1.f / D_);
    float var  = ss * (1.f / D_) - mean * mean;
    float inv  = rsqrtf(var + 1e-5f);
    float4 g4 = *(const float4*)(g + tid * 4);
    float4 b4 = *(const float4*)(bta + tid * 4);
    float4 o;
    o.x = (v.x - mean) * inv * g4.x + b4.x;
    o.y = (v.y - mean) * inv * g4.y + b4.y;
    o.z = (v.z - mean) * inv * g4.z + b4.z;
    o.w = (v.w - mean) * inv * g4.w + b4.w;
    *(float4*)(out + (size_t)row * D_ + tid * 4) = o;
}

// ---------------- launch ---------------------------------------------------
extern "C" void kernel_launch(void* const* d_in, const int* in_sizes, int n_in,
                              void* d_out, int out_size)
{
    const float* x      = (const float*)d_in[0];
    const int*   t_len  = (const int*)d_in[1];
    const int*   ridx   = (const int*)d_in[2];
    const float* conv_w = (const float*)d_in[3];
    const float* bn_g   = (const float*)d_in[4];
    const float* bn_b   = (const float*)d_in[5];
    const float* bn_m   = (const float*)d_in[6];
    const float* bn_v   = (const float*)d_in[7];
    const float* wq = (const float*)d_in[8];  const float* bq = (const float*)d_in[9];
    const float* wk = (const float*)d_in[10]; const float* bk = (const float*)d_in[11];
    const float* wv = (const float*)d_in[12]; const float* bv = (const float*)d_in[13];
    const float* wo = (const float*)d_in[14]; const float* bo = (const float*)d_in[15];
    const float* ln1g = (const float*)d_in[16]; const float* ln1b = (const float*)d_in[17];
    const float* w1 = (const float*)d_in[18]; const float* b1 = (const float*)d_in[19];
    const float* w2 = (const float*)d_in[20]; const float* b2 = (const float*)d_in[21];
    const float* ln2g = (const float*)d_in[22]; const float* ln2b = (const float*)d_in[23];
    float* out = (float*)d_out;

    float *xc, *q, *k, *v, *attn, *x1, *tmp, *hbuf;
    float *wtq, *wtk, *wtv, *wto, *wt1, *wt2;
    cudaGetSymbolAddress((void**)&xc,   g_xc);
    cudaGetSymbolAddress((void**)&q,    g_q);
    cudaGetSymbolAddress((void**)&k,    g_k);
    cudaGetSymbolAddress((void**)&v,    g_v);
    cudaGetSymbolAddress((void**)&attn, g_attn);
    cudaGetSymbolAddress((void**)&x1,   g_x1);
    cudaGetSymbolAddress((void**)&tmp,  g_tmp);
    cudaGetSymbolAddress((void**)&hbuf, g_h);
    cudaGetSymbolAddress((void**)&wtq,  g_wtq);
    cudaGetSymbolAddress((void**)&wtk,  g_wtk);
    cudaGetSymbolAddress((void**)&wtv,  g_wtv);
    cudaGetSymbolAddress((void**)&wto,  g_wto);
    cudaGetSymbolAddress((void**)&wt1,  g_wt1);
    cudaGetSymbolAddress((void**)&wt2,  g_wt2);

    cudaFuncSetAttribute(attn_kernel, cudaFuncAttributeMaxDynamicSharedMemorySize, ATTN_SMEM);
    cudaFuncSetAttribute(tf32_gemm_kernel, cudaFuncAttributeMaxDynamicSharedMemorySize, GEMM_SMEM);

    // 0. weight transposes ([K,N] -> [N,K])
    transpose_kernel<<<dim3(D_/32, D_/32), 256>>>(wq, wtq, D_, D_);
    transpose_kernel<<<dim3(D_/32, D_/32), 256>>>(wk, wtk, D_, D_);
    transpose_kernel<<<dim3(D_/32, D_/32), 256>>>(wv, wtv, D_, D_);
    transpose_kernel<<<dim3(D_/32, D_/32), 256>>>(wo, wto, D_, D_);
    transpose_kernel<<<dim3(2*D_/32, D_/32), 256>>>(w1, wt1, D_, 2*D_);
    transpose_kernel<<<dim3(D_/32, 2*D_/32), 256>>>(w2, wt2, 2*D_, D_);

    // 1. conv + residual + BN
    conv_bn_kernel<<<(M_ * D_) / 256, 256>>>(x, conv_w, bn_g, bn_b, bn_m, bn_v);

    // 2. Q/K/V projections (3xTF32 mma.sync)
    dim3 g512(D_ / 128, M_ / 128);       // (4, 256)
    tf32_gemm_kernel<<<g512, 256, GEMM_SMEM>>>(xc, wtq, bq, nullptr, q, M_, D_, D_, 0);
    tf32_gemm_kernel<<<g512, 256, GEMM_SMEM>>>(xc, wtk, bk, nullptr, k, M_, D_, D_, 0);
    tf32_gemm_kernel<<<g512, 256, GEMM_SMEM>>>(xc, wtv, bv, nullptr, v, M_, D_, D_, 0);

    // 3. bucketed sparse attention
    attn_kernel<<<dim3(NB_, H_, B_), 256, ATTN_SMEM>>>(q, k, v, t_len, ridx, attn);

    // 4. output projection + bias + residual(xc), then LN1
    tf32_gemm_kernel<<<g512, 256, GEMM_SMEM>>>(attn, wto, bo, xc, tmp, M_, D_, D_, 0);
    ln_kernel<<<M_, 128>>>(tmp, ln1g, ln1b, x1);

    // 5. MLP: gelu(x1@w1+b1) @ w2 + b2 + x1, then LN2 -> out
    dim3 g1024(2 * D_ / 128, M_ / 128);  // (8, 256)
    tf32_gemm_kernel<<<g1024, 256, GEMM_SMEM>>>(x1, wt1, b1, nullptr, hbuf, M_, 2 * D_, D_, 1);
    tf32_gemm_kernel<<<g512, 256, GEMM_SMEM>>>(hbuf, wt2, b2, x1, tmp, M_, D_, 2 * D_, 0);
    ln_kernel<<<M_, 128>>>(tmp, ln2g, ln2b, out);
}